// round 6
// baseline (speedup 1.0000x reference)
#include <cuda_runtime.h>
#include <cuda_fp16.h>
#include <stdint.h>

// ---------------- problem constants ----------------
#define NNODES 50000
#define NEDGES 1000000
#define HID    128
#define KDIM   288            // 273 padded to 18 * 16
#define KSTEPS 18
#define STRH   296            // halves per smem row (592 B; 592 % 128 = 80 -> conflict-free ldmatrix)
#define STRB   592            // bytes per smem row
#define GROUPS32 (NEDGES / 32) // 31250, exact
#define WPB    16             // warps per block (8 pairs)
#define THREADS 512

// ---------------- smem layout (byte offsets) ----------------
#define SOFF_A    0            // 256 rows * 592 = 151552 (row bytes: 0..511 feat, 512..543 ea, 544..547 dist,
                               //  548..575 zero-pad, 576..587 partials)
#define SOFF_B    151552       // 128 rows * 592 = 75776  -> ends 227328
#define SOFF_B1   227328       // 128 f32 = 512
#define SOFF_W2   227840       // 384 f32 = 1536
#define SOFF_B2   229376       // 16
#define SMEM_DYN  229392
#define PAD_OFF   576

// ---------------- device globals (no allocation allowed) ----------------
__device__ __half g_featH[(size_t)NNODES * HID];   // 12.8 MB
__device__ __half g_eaH[(size_t)NEDGES * 16];      // 32 MB, fp16 edge_attr
__device__ __half g_W1h[HID * KDIM];               // [n][k] fp16, zero-padded k>=273
__device__ float  g_cnt[NNODES];

static __device__ __forceinline__ uint32_t smem_u32(const void* p) {
    uint32_t a;
    asm("{ .reg .u64 t; cvta.to.shared.u64 t, %1; cvt.u32.u64 %0, t; }" : "=r"(a) : "l"(p));
    return a;
}
static __device__ __forceinline__ float silu(float x) { return x / (1.f + __expf(-x)); }
static __device__ __forceinline__ void pair_bar(int id) {
    asm volatile("bar.sync %0, 64;" :: "r"(id) : "memory");
}
#define CP16(dst, src) asm volatile("cp.async.ca.shared.global [%0], [%1], 16;" :: "r"(dst), "l"(src) : "memory")
#define CP_COMMIT()    asm volatile("cp.async.commit_group;" ::: "memory")
#define CP_WAIT0()     asm volatile("cp.async.wait_group 0;" ::: "memory")

// ---------------- prep kernels ----------------
__global__ void prep_feat_kernel(const float* __restrict__ nf) {
    int i = blockIdx.x * blockDim.x + threadIdx.x;
    const int tot = NNODES * HID / 2;
    if (i < tot) {
        float2 v = reinterpret_cast<const float2*>(nf)[i];
        reinterpret_cast<__half2*>(g_featH)[i] = __floats2half2_rn(v.x, v.y);
    }
}
__global__ void prep_ea_kernel(const float* __restrict__ ea) {
    size_t i = (size_t)blockIdx.x * blockDim.x + threadIdx.x;
    const size_t tot = (size_t)NEDGES * 16 / 2;
    if (i < tot) {
        float2 v = reinterpret_cast<const float2*>(ea)[i];
        reinterpret_cast<__half2*>(g_eaH)[i] = __floats2half2_rn(v.x, v.y);
    }
}
// our k-order: [0..127]=feat_row, [128..255]=feat_col, [256..271]=edge_attr, [272]=dist, pad->288
__global__ void prep_w1_kernel(const float* __restrict__ W1) {
    int idx = blockIdx.x * blockDim.x + threadIdx.x;
    if (idx >= HID * KDIM) return;
    int n = idx / KDIM, k = idx % KDIM;
    float v = 0.f;
    if (k < 273) {
        int orig = (k == 272) ? 0 : (k + 1);
        v = W1[orig * HID + n];
    }
    g_W1h[n * KDIM + k] = __float2half(v);
}
__global__ void zero_kernel(float* __restrict__ out) {
    int i = blockIdx.x * blockDim.x + threadIdx.x;
    int stride = gridDim.x * blockDim.x;
    for (int j = i; j < NNODES * 9; j += stride) out[j] = 0.f;
    for (int j = i; j < NNODES; j += stride) g_cnt[j] = 0.f;
}
__global__ void finalize_kernel(float* __restrict__ out) {
    int i = blockIdx.x * blockDim.x + threadIdx.x;
    int stride = gridDim.x * blockDim.x;
    for (int j = i; j < NNODES * 9; j += stride)
        out[j] = out[j] / fmaxf(g_cnt[j / 9], 1.0f);
}

// ---------------- main persistent kernel ----------------
__global__ void __launch_bounds__(THREADS, 1)
edge_kernel(const float* __restrict__ pos,
            const float* __restrict__ b1,
            const float* __restrict__ W2,
            const float* __restrict__ b2,
            const int*   __restrict__ ei,
            float*       __restrict__ out)
{
    extern __shared__ char sm[];
    const uint32_t smb = smem_u32(sm);
    const int tid = threadIdx.x;
    const int wid = tid >> 5;
    const int lid = tid & 31;
    const int pairL = wid >> 1;
    const int par   = wid & 1;

    // stage W1 [n][k] fp16 into smem with padded row stride
    {
        const uint32_t* src = reinterpret_cast<const uint32_t*>(g_W1h);
        uint32_t* dst = reinterpret_cast<uint32_t*>(sm + SOFF_B);
        for (int i = tid; i < HID * (KDIM / 2); i += THREADS) {
            int n = i / (KDIM / 2), k2 = i % (KDIM / 2);
            dst[n * (STRH / 2) + k2] = src[i];
        }
    }
    float* b1s = reinterpret_cast<float*>(sm + SOFF_B1);
    float* w2s = reinterpret_cast<float*>(sm + SOFF_W2);
    float* b2s = reinterpret_cast<float*>(sm + SOFF_B2);
    if (tid < HID) b1s[tid] = b1[tid];
    for (int i = tid; i < HID * 3; i += THREADS) w2s[i] = W2[i];
    if (tid < 3) b2s[tid] = b2[tid];

    const int slabRow0 = pairL * 32;
    const int ownRow0  = slabRow0 + par * 16;
    __half* Aw = reinterpret_cast<__half*>(sm + SOFF_A) + ownRow0 * STRH;
    const uint32_t aOwnB = smb + SOFF_A + (uint32_t)ownRow0 * STRB;
    const char* fH = (const char*)g_featH;
    const char* eH = (const char*)g_eaH;

    // one-time zero fill of halves 274..287 in own rows (never overwritten later)
    if (lid < 16) {
        __half* Ar = Aw + lid * STRH;
        #pragma unroll
        for (int k2 = 274; k2 < 288; k2 += 2)
            *reinterpret_cast<uint32_t*>(Ar + k2) = 0u;
    }
    __syncthreads();

    // ldmatrix lane address templates
    const int arow = (lid & 7) + ((lid >> 3) & 1) * 8;
    const int acol = ((lid >> 4) & 1) * 8;
    const uint32_t aAddrMt0 = smb + SOFF_A + (uint32_t)(slabRow0 + arow) * STRB + acol * 2;
    const uint32_t aAddrMt1 = aAddrMt0 + 16u * STRB;
    const int brow = (lid & 7) + ((lid >> 4) & 1) * 8;
    const int bcol16 = ((lid >> 3) & 1) * 16;
    const int nhalf = par * 64;
    const uint32_t bAddr0 = smb + SOFF_B + (uint32_t)(nhalf + brow) * STRB + bcol16;

    const int barId = pairL + 1;
    const int gq = lid >> 2;
    const int gstride = gridDim.x * (WPB / 2);
    const int g0 = blockIdx.x * (WPB / 2) + pairL;

    // ---- prologue: meta + async gather for first group ----
    int r_reg = 0, c_reg = 0, rn_reg = 0;
    float dxr = 0.f, dyr = 0.f, dzr = 0.f, ddr = 0.f;
    {
        const int e0own = g0 * 32 + par * 16;
        if (lid < 16) {
            r_reg = ei[e0own + lid];
            c_reg = ei[NEDGES + e0own + lid];
            rn_reg = r_reg;
        }
        __syncwarp();
        #pragma unroll
        for (int i = 0; i < 16; ++i) {
            int r = __shfl_sync(0xffffffffu, r_reg, i);
            int c = __shfl_sync(0xffffffffu, c_reg, i);
            uint32_t dRow = aOwnB + (uint32_t)i * STRB;
            if (lid < 16) CP16(dRow + lid * 16, fH + (size_t)r * 256 + lid * 16);
            else          CP16(dRow + 256 + (lid - 16) * 16, fH + (size_t)c * 256 + (lid - 16) * 16);
        }
        {
            int row = lid >> 1, hb = (lid & 1) * 16;
            CP16(aOwnB + (uint32_t)row * STRB + 512 + hb, eH + (size_t)(e0own + row) * 32 + hb);
        }
        CP_COMMIT();
        if (lid < 16) {
            dxr = pos[3 * r_reg + 0] - pos[3 * c_reg + 0];
            dyr = pos[3 * r_reg + 1] - pos[3 * c_reg + 1];
            dzr = pos[3 * r_reg + 2] - pos[3 * c_reg + 2];
            ddr = sqrtf(dxr * dxr + dyr * dyr + dzr * dzr);
            *reinterpret_cast<__half2*>(Aw + lid * STRH + 272) = __floats2half2_rn(ddr, 0.f);
        }
    }

    for (int g = g0; g < GROUPS32; g += gstride) {
        const int gn = g + gstride;
        const bool hasN = gn < GROUPS32;
        // prefetch next group's indices early (latency covered by MMA phase)
        int rN = 0, cN = 0;
        if (hasN && lid < 16) {
            int eN = gn * 32 + par * 16 + lid;
            rN = ei[eN];
            cN = ei[NEDGES + eN];
        }

        CP_WAIT0();
        pair_bar(barId);   // A slab (32 rows) fully built & visible to both warps

        // ---- GEMM1: D[32 x 64] = A_pair[32x288] * W1half^T ----
        float acc[2][8][4];
        #pragma unroll
        for (int mt = 0; mt < 2; ++mt)
            #pragma unroll
            for (int nt = 0; nt < 8; ++nt) {
                acc[mt][nt][0] = 0.f; acc[mt][nt][1] = 0.f;
                acc[mt][nt][2] = 0.f; acc[mt][nt][3] = 0.f;
            }
        uint32_t aA0 = aAddrMt0, aA1 = aAddrMt1, bA = bAddr0;
        #pragma unroll 1
        for (int ks = 0; ks < KSTEPS; ++ks) {
            uint32_t x0, x1, x2, x3, y0, y1, y2, y3;
            asm volatile("ldmatrix.sync.aligned.m8n8.x4.shared.b16 {%0,%1,%2,%3}, [%4];"
                         : "=r"(x0), "=r"(x1), "=r"(x2), "=r"(x3) : "r"(aA0));
            asm volatile("ldmatrix.sync.aligned.m8n8.x4.shared.b16 {%0,%1,%2,%3}, [%4];"
                         : "=r"(y0), "=r"(y1), "=r"(y2), "=r"(y3) : "r"(aA1));
            #pragma unroll
            for (int j = 0; j < 4; ++j) {
                uint32_t b0, b1r, b2r, b3;
                asm volatile("ldmatrix.sync.aligned.m8n8.x4.shared.b16 {%0,%1,%2,%3}, [%4];"
                             : "=r"(b0), "=r"(b1r), "=r"(b2r), "=r"(b3)
                             : "r"(bA + (uint32_t)j * 16 * STRB));
                asm volatile("mma.sync.aligned.m16n8k16.row.col.f32.f16.f16.f32 "
                             "{%0,%1,%2,%3}, {%4,%5,%6,%7}, {%8,%9}, {%0,%1,%2,%3};"
                             : "+f"(acc[0][2*j][0]), "+f"(acc[0][2*j][1]), "+f"(acc[0][2*j][2]), "+f"(acc[0][2*j][3])
                             : "r"(x0), "r"(x1), "r"(x2), "r"(x3), "r"(b0), "r"(b1r));
                asm volatile("mma.sync.aligned.m16n8k16.row.col.f32.f16.f16.f32 "
                             "{%0,%1,%2,%3}, {%4,%5,%6,%7}, {%8,%9}, {%0,%1,%2,%3};"
                             : "+f"(acc[0][2*j+1][0]), "+f"(acc[0][2*j+1][1]), "+f"(acc[0][2*j+1][2]), "+f"(acc[0][2*j+1][3])
                             : "r"(x0), "r"(x1), "r"(x2), "r"(x3), "r"(b2r), "r"(b3));
                asm volatile("mma.sync.aligned.m16n8k16.row.col.f32.f16.f16.f32 "
                             "{%0,%1,%2,%3}, {%4,%5,%6,%7}, {%8,%9}, {%0,%1,%2,%3};"
                             : "+f"(acc[1][2*j][0]), "+f"(acc[1][2*j][1]), "+f"(acc[1][2*j][2]), "+f"(acc[1][2*j][3])
                             : "r"(y0), "r"(y1), "r"(y2), "r"(y3), "r"(b0), "r"(b1r));
                asm volatile("mma.sync.aligned.m16n8k16.row.col.f32.f16.f16.f32 "
                             "{%0,%1,%2,%3}, {%4,%5,%6,%7}, {%8,%9}, {%0,%1,%2,%3};"
                             : "+f"(acc[1][2*j+1][0]), "+f"(acc[1][2*j+1][1]), "+f"(acc[1][2*j+1][2]), "+f"(acc[1][2*j+1][3])
                             : "r"(y0), "r"(y1), "r"(y2), "r"(y3), "r"(b2r), "r"(b3));
            }
            aA0 += 32; aA1 += 32; bA += 32;
        }
        pair_bar(barId);   // both warps done reading A: slab reusable

        // ---- issue next group's async gather (overlaps with epilogue below) ----
        float dxN = 0.f, dyN = 0.f, dzN = 0.f, ddN = 0.f;
        if (hasN) {
            const int e0n = gn * 32 + par * 16;
            #pragma unroll
            for (int i = 0; i < 16; ++i) {
                int r = __shfl_sync(0xffffffffu, rN, i);
                int c = __shfl_sync(0xffffffffu, cN, i);
                uint32_t dRow = aOwnB + (uint32_t)i * STRB;
                if (lid < 16) CP16(dRow + lid * 16, fH + (size_t)r * 256 + lid * 16);
                else          CP16(dRow + 256 + (lid - 16) * 16, fH + (size_t)c * 256 + (lid - 16) * 16);
            }
            {
                int row = lid >> 1, hb = (lid & 1) * 16;
                CP16(aOwnB + (uint32_t)row * STRB + 512 + hb, eH + (size_t)(e0n + row) * 32 + hb);
            }
            CP_COMMIT();
            if (lid < 16) {
                dxN = pos[3 * rN + 0] - pos[3 * cN + 0];
                dyN = pos[3 * rN + 1] - pos[3 * cN + 1];
                dzN = pos[3 * rN + 2] - pos[3 * cN + 2];
                ddN = sqrtf(dxN * dxN + dyN * dyN + dzN * dzN);
                *reinterpret_cast<__half2*>(Aw + lid * STRH + 272) = __floats2half2_rn(ddN, 0.f);
            }
        }

        // ---- partial epilogue: silu(h+b1), dot with W2 over this warp's 64 n's ----
        float pr[2][2][3];
        #pragma unroll
        for (int mt = 0; mt < 2; ++mt)
            #pragma unroll
            for (int hf = 0; hf < 2; ++hf) {
                pr[mt][hf][0] = 0.f; pr[mt][hf][1] = 0.f; pr[mt][hf][2] = 0.f;
            }
        const int cbase = (lid & 3) * 2;
        #pragma unroll
        for (int mt = 0; mt < 2; ++mt) {
            #pragma unroll
            for (int nt = 0; nt < 8; ++nt) {
                int n = nhalf + nt * 8 + cbase;
                float h0 = silu(acc[mt][nt][0] + b1s[n]);
                float h1 = silu(acc[mt][nt][1] + b1s[n + 1]);
                float h2 = silu(acc[mt][nt][2] + b1s[n]);
                float h3 = silu(acc[mt][nt][3] + b1s[n + 1]);
                float wa0 = w2s[n * 3 + 0], wb0 = w2s[n * 3 + 1], wc0 = w2s[n * 3 + 2];
                float wa1 = w2s[n * 3 + 3], wb1 = w2s[n * 3 + 4], wc1 = w2s[n * 3 + 5];
                pr[mt][0][0] += h0 * wa0 + h1 * wa1;
                pr[mt][0][1] += h0 * wb0 + h1 * wb1;
                pr[mt][0][2] += h0 * wc0 + h1 * wc1;
                pr[mt][1][0] += h2 * wa0 + h3 * wa1;
                pr[mt][1][1] += h2 * wb0 + h3 * wb1;
                pr[mt][1][2] += h2 * wc0 + h3 * wc1;
            }
        }
        #pragma unroll
        for (int off = 1; off <= 2; off <<= 1) {
            #pragma unroll
            for (int mt = 0; mt < 2; ++mt)
                #pragma unroll
                for (int hf = 0; hf < 2; ++hf) {
                    pr[mt][hf][0] += __shfl_xor_sync(0xffffffffu, pr[mt][hf][0], off);
                    pr[mt][hf][1] += __shfl_xor_sync(0xffffffffu, pr[mt][hf][1], off);
                    pr[mt][hf][2] += __shfl_xor_sync(0xffffffffu, pr[mt][hf][2], off);
                }
        }

        // deposit partials for the NON-owned mt into those rows' pad bytes
        const int mtNon = 1 - par;
        if ((lid & 3) == 0) {
            #pragma unroll
            for (int hf = 0; hf < 2; ++hf) {
                int rowNon = slabRow0 + mtNon * 16 + gq + hf * 8;
                float* pad = reinterpret_cast<float*>(sm + SOFF_A + (size_t)rowNon * STRB + PAD_OFF);
                pad[0] = pr[mtNon][hf][0];
                pad[1] = pr[mtNon][hf][1];
                pad[2] = pr[mtNon][hf][2];
            }
        }
        pair_bar(barId);   // partials visible

        // ---- final epilogue for this warp's own 16 edges ----
        const float s3 = 1.7320508075688772f;
        const int mtOwn = par;
        #pragma unroll
        for (int hf = 0; hf < 2; ++hf) {
            int rloc = gq + hf * 8;
            float ddx = __shfl_sync(0xffffffffu, dxr, rloc);
            float ddy = __shfl_sync(0xffffffffu, dyr, rloc);
            float ddz = __shfl_sync(0xffffffffu, dzr, rloc);
            float ddd = __shfl_sync(0xffffffffu, ddr, rloc);
            int   rn  = __shfl_sync(0xffffffffu, rn_reg, rloc);
            if ((lid & 3) == 0) {
                int rowOwn = ownRow0 + rloc;
                const float* pad = reinterpret_cast<const float*>(sm + SOFF_A + (size_t)rowOwn * STRB + PAD_OFF);
                float pa = pr[mtOwn][hf][0] + pad[0];
                float pb = pr[mtOwn][hf][1] + pad[1];
                float pc = pr[mtOwn][hf][2] + pad[2];
                float w0 = silu(pa + b2s[0]);
                float w1 = silu(pb + b2s[1]);
                float w2v = silu(pc + b2s[2]);
                float inv = 1.f / fmaxf(ddd, 1e-12f);
                float x = ddx * inv, y = ddy * inv, z = ddz * inv;
                float* o = out + (size_t)rn * 9;
                atomicAdd(o + 0, w0);
                atomicAdd(o + 1, x * w1);
                atomicAdd(o + 2, y * w1);
                atomicAdd(o + 3, z * w1);
                atomicAdd(o + 4, s3 * x * z * w2v);
                atomicAdd(o + 5, s3 * x * y * w2v);
                atomicAdd(o + 6, (y * y - 0.5f * (x * x + z * z)) * w2v);
                atomicAdd(o + 7, s3 * y * z * w2v);
                atomicAdd(o + 8, 0.5f * s3 * (z * z - x * x) * w2v);
                atomicAdd(&g_cnt[rn], 1.0f);
            }
        }

        // rotate next-group meta into current
        r_reg = rN; c_reg = cN; rn_reg = rN;
        dxr = dxN; dyr = dyN; dzr = dzN; ddr = ddN;
    }
}

// ---------------- launch ----------------
extern "C" void kernel_launch(void* const* d_in, const int* in_sizes, int n_in,
                              void* d_out, int out_size) {
    const float* node_feat = (const float*)d_in[0];
    const float* node_pos  = (const float*)d_in[1];
    const float* edge_attr = (const float*)d_in[2];
    const float* W1        = (const float*)d_in[3];
    const float* b1        = (const float*)d_in[4];
    const float* W2        = (const float*)d_in[5];
    const float* b2        = (const float*)d_in[6];
    const int*   ei        = (const int*)d_in[7];
    float* out = (float*)d_out;

    cudaFuncSetAttribute(edge_kernel,
                         cudaFuncAttributeMaxDynamicSharedMemorySize, SMEM_DYN);

    zero_kernel<<<512, 256>>>(out);
    prep_feat_kernel<<<(NNODES * HID / 2 + 255) / 256, 256>>>(node_feat);
    prep_ea_kernel<<<(NEDGES * 16 / 2 + 255) / 256, 256>>>(edge_attr);
    prep_w1_kernel<<<(HID * KDIM + 255) / 256, 256>>>(W1);
    edge_kernel<<<152, THREADS, SMEM_DYN>>>(node_pos, b1, W2, b2, ei, out);
    finalize_kernel<<<512, 256>>>(out);
}

// round 8
// speedup vs baseline: 2.3294x; 2.3294x over previous
#include <cuda_runtime.h>
#include <cuda_fp16.h>
#include <stdint.h>

// ---------------- problem constants ----------------
#define NNODES 50000
#define NEDGES 1000000
#define HID    128
#define THREADS 512
#define WPB    16
#define GROUPS (NEDGES / 16)   // 62500, exact

// ---------------- main-kernel smem layout ----------------
#define S_STRIDE  272                         // 128 halves + 16B pad
#define SOFF_S    0                           // 16 warps * 16 rows * 272 = 69632
#define EA_STRIDE 48
#define SOFF_EA   69632                       // 16*16*48 = 12288 -> 81920
#define W1C_STRIDE 48
#define SOFF_W1C  81920                       // 128*48 = 6144 -> 88064
#define W2T_STRIDE 272
#define SOFF_W2T  88064                       // 8*272 = 2176 -> 90240
#define SMEM_MAIN 90240

// ---------------- prep_P smem layout ----------------
#define PP_BSTR    272
#define PP_SOFF_BA 0                          // 128*272 = 34816
#define PP_SOFF_BB 34816
#define PP_SOFF_AS 69632                      // 16 warps * 16 rows * 272 = 69632
#define PP_SMEM    139264

// ---------------- device globals ----------------
__device__ __half g_featH[(size_t)NNODES * HID];
__device__ __half g_P1[(size_t)NNODES * HID];     // feat @ W1a^T + b1 (fp16)
__device__ __half g_P2[(size_t)NNODES * HID];     // feat @ W1b^T      (fp16)
__device__ __half g_W1ab[2 * 128 * 128];          // [m][n][k] fp16
__device__ __half g_W1cT[128 * 16];               // [n][k] ea weights
__device__ __half g_W2T[8 * 128];                 // [n(pad8)][k] W2 transposed
__device__ float  g_W1d[128];                     // dist weights
__device__ float  g_cnt[NNODES];

static __device__ __forceinline__ uint32_t smem_u32(const void* p) {
    uint32_t a;
    asm("{ .reg .u64 t; cvta.to.shared.u64 t, %1; cvt.u32.u64 %0, t; }" : "=r"(a) : "l"(p));
    return a;
}
static __device__ __forceinline__ float silu(float x) { return x / (1.f + __expf(-x)); }
// silu on a half2: a = x/2; r = a + a*tanh(a)  (1 MUFU per 2 values)
static __device__ __forceinline__ uint32_t silu_h2(uint32_t x) {
    uint32_t a, t, r;
    asm("mul.rn.f16x2 %0, %1, %2;" : "=r"(a) : "r"(x), "r"(0x38003800u));
    asm("tanh.approx.f16x2 %0, %1;" : "=r"(t) : "r"(a));
    asm("fma.rn.f16x2 %0, %1, %2, %3;" : "=r"(r) : "r"(a), "r"(t), "r"(a));
    return r;
}

#define LDSM_X4(r0,r1,r2,r3,addr) \
    asm volatile("ldmatrix.sync.aligned.m8n8.x4.shared.b16 {%0,%1,%2,%3}, [%4];" \
                 : "=r"(r0), "=r"(r1), "=r"(r2), "=r"(r3) : "r"(addr))
#define MMA16816(d0,d1,d2,d3,a0,a1,a2,a3,b0,b1) \
    asm volatile("mma.sync.aligned.m16n8k16.row.col.f32.f16.f16.f32 " \
                 "{%0,%1,%2,%3}, {%4,%5,%6,%7}, {%8,%9}, {%0,%1,%2,%3};" \
                 : "+f"(d0), "+f"(d1), "+f"(d2), "+f"(d3) \
                 : "r"(a0), "r"(a1), "r"(a2), "r"(a3), "r"(b0), "r"(b1))

// ---------------- prep kernels ----------------
__global__ void prep_feat_kernel(const float* __restrict__ nf) {
    int i = blockIdx.x * blockDim.x + threadIdx.x;
    const int tot = NNODES * HID / 2;
    if (i < tot) {
        float2 v = reinterpret_cast<const float2*>(nf)[i];
        reinterpret_cast<__half2*>(g_featH)[i] = __floats2half2_rn(v.x, v.y);
    }
}

// msg order: [0]=dist, [1..128]=feat_row, [129..256]=feat_col, [257..272]=ea
__global__ void prep_w_kernel(const float* __restrict__ W1, const float* __restrict__ W2) {
    int idx = blockIdx.x * blockDim.x + threadIdx.x;
    if (idx < 32768) {
        int m = idx >> 14, n = (idx >> 7) & 127, k = idx & 127;
        g_W1ab[idx] = __float2half(W1[(1 + m * 128 + k) * HID + n]);
    } else if (idx < 34816) {
        int j = idx - 32768; int n = j >> 4, c = j & 15;
        g_W1cT[j] = __float2half(W1[(257 + c) * HID + n]);
    } else if (idx < 35840) {
        int j = idx - 34816; int nr = j >> 7, k = j & 127;
        g_W2T[j] = __float2half(nr < 3 ? W2[k * 3 + nr] : 0.f);
    } else if (idx < 35968) {
        int j = idx - 35840;
        g_W1d[j] = W1[j];     // W1[0][n]
    }
}

__global__ void zero_kernel(float* __restrict__ out) {
    int i = blockIdx.x * blockDim.x + threadIdx.x;
    int stride = gridDim.x * blockDim.x;
    for (int j = i; j < NNODES * 9; j += stride) out[j] = 0.f;
    for (int j = i; j < NNODES; j += stride) g_cnt[j] = 0.f;
}

__global__ void finalize_kernel(float* __restrict__ out) {
    int i = blockIdx.x * blockDim.x + threadIdx.x;
    int stride = gridDim.x * blockDim.x;
    for (int j = i; j < NNODES * 9; j += stride)
        out[j] = out[j] / fmaxf(g_cnt[j / 9], 1.0f);
}

// ---------------- P precompute: P1 = feat @ W1a^T + b1, P2 = feat @ W1b^T ----------------
__global__ void __launch_bounds__(512, 1)
prep_P_kernel(const float* __restrict__ b1) {
    extern __shared__ char sm[];
    const uint32_t smb = smem_u32(sm);
    int tid = threadIdx.x, wid = tid >> 5, lid = tid & 31;

    {   // stage both B matrices (128 rows x 256B -> stride 272)
        const uint4* srcA = (const uint4*)g_W1ab;
        const uint4* srcB = (const uint4*)(g_W1ab + 16384);
        for (int i = tid; i < 2048; i += 512) {
            int row = i >> 4, p = i & 15;
            *(uint4*)(sm + PP_SOFF_BA + row * PP_BSTR + p * 16) = srcA[i];
            *(uint4*)(sm + PP_SOFF_BB + row * PP_BSTR + p * 16) = srcB[i];
        }
    }
    __syncthreads();

    int t = blockIdx.x * 16 + wid;
    if (t >= 3125) return;     // 3125*16 = 50000 exact
    int node0 = t * 16;
    char* Aw = sm + PP_SOFF_AS + wid * 16 * PP_BSTR;

    for (int i = 0; i < 16; ++i) {
        uint2 v = ((const uint2*)(g_featH + (size_t)(node0 + i) * HID))[lid];
        *(uint2*)(Aw + i * PP_BSTR + lid * 8) = v;
    }
    __syncwarp();

    const uint32_t aBase = smb + PP_SOFF_AS + (uint32_t)wid * 16 * PP_BSTR
                         + (uint32_t)((lid & 7) + ((lid >> 3) & 1) * 8) * PP_BSTR
                         + ((lid >> 4) & 1) * 16;
    const uint32_t bRowOff = (uint32_t)((lid & 7) + ((lid >> 4) & 1) * 8) * PP_BSTR
                           + ((lid >> 3) & 1) * 16;
    const int gq = lid >> 2, tq = lid & 3;

    #pragma unroll 1
    for (int mat = 0; mat < 2; ++mat) {
        uint32_t bBase = smb + (mat ? PP_SOFF_BB : PP_SOFF_BA) + bRowOff;
        __half* OUT = mat ? g_P2 : g_P1;
        float acc[16][4];
        #pragma unroll
        for (int nt = 0; nt < 16; ++nt) { acc[nt][0]=0.f; acc[nt][1]=0.f; acc[nt][2]=0.f; acc[nt][3]=0.f; }
        #pragma unroll 1
        for (int ks = 0; ks < 8; ++ks) {
            uint32_t a0,a1,a2,a3;
            LDSM_X4(a0,a1,a2,a3, aBase + ks * 32);
            #pragma unroll
            for (int j = 0; j < 8; ++j) {     // FIX: 8 n-blocks of 16 -> full 128 columns
                uint32_t b0,b1r,b2,b3;
                LDSM_X4(b0,b1r,b2,b3, bBase + (uint32_t)j * 16 * PP_BSTR + ks * 32);
                MMA16816(acc[2*j][0],acc[2*j][1],acc[2*j][2],acc[2*j][3], a0,a1,a2,a3, b0,b1r);
                MMA16816(acc[2*j+1][0],acc[2*j+1][1],acc[2*j+1][2],acc[2*j+1][3], a0,a1,a2,a3, b2,b3);
            }
        }
        #pragma unroll
        for (int nt = 0; nt < 16; ++nt) {
            int col = nt * 8 + tq * 2;
            float bx = 0.f, by = 0.f;
            if (mat == 0) { bx = b1[col]; by = b1[col + 1]; }
            __half2 v0 = __floats2half2_rn(acc[nt][0] + bx, acc[nt][1] + by);
            __half2 v1 = __floats2half2_rn(acc[nt][2] + bx, acc[nt][3] + by);
            *(__half2*)(OUT + (size_t)(node0 + gq)     * HID + col) = v0;
            *(__half2*)(OUT + (size_t)(node0 + gq + 8) * HID + col) = v1;
        }
    }
}

// ---------------- main edge kernel ----------------
__global__ void __launch_bounds__(THREADS, 1)
edge_kernel(const float* __restrict__ pos,
            const float* __restrict__ edge_attr,
            const float* __restrict__ b2,
            const int*   __restrict__ ei,
            float*       __restrict__ out)
{
    extern __shared__ char sm[];
    const uint32_t smb = smem_u32(sm);
    const int tid = threadIdx.x, wid = tid >> 5, lid = tid & 31;

    // stage W1cT (128 rows x 32B, stride 48) and W2T (8 rows x 256B, stride 272)
    for (int i = tid; i < 256; i += THREADS) {
        int row = i >> 1, p = i & 1;
        *(uint4*)(sm + SOFF_W1C + row * W1C_STRIDE + p * 16) = ((const uint4*)g_W1cT)[i];
    }
    for (int i = tid; i < 128; i += THREADS) {
        int row = i >> 4, p = i & 15;
        *(uint4*)(sm + SOFF_W2T + row * W2T_STRIDE + p * 16) = ((const uint4*)g_W2T)[i];
    }
    // per-lane dist-weight constants (lane covers S cols 4*lid..4*lid+3), half2
    const __half2 w1dA = __floats2half2_rn(g_W1d[4*lid],     g_W1d[4*lid + 1]);
    const __half2 w1dB = __floats2half2_rn(g_W1d[4*lid + 2], g_W1d[4*lid + 3]);
    const float b20 = b2[0], b21 = b2[1], b22 = b2[2];
    __syncthreads();

    // W2 B-frags, permanent in registers (8 ksteps x 2 regs)
    uint32_t b2f[8][2];
    {
        uint32_t addr = smb + SOFF_W2T + (uint32_t)(lid & 7) * W2T_STRIDE + ((lid >> 3) & 1) * 16;
        #pragma unroll
        for (int s = 0; s < 8; ++s)
            asm volatile("ldmatrix.sync.aligned.m8n8.x2.shared.b16 {%0,%1}, [%2];"
                         : "=r"(b2f[s][0]), "=r"(b2f[s][1]) : "r"(addr + s * 32));
    }

    char* Sw  = sm + SOFF_S  + (size_t)wid * 16 * S_STRIDE;
    char* eaW = sm + SOFF_EA + (size_t)wid * 16 * EA_STRIDE;
    const uint32_t eaU = smb + SOFF_EA + (uint32_t)wid * 16 * EA_STRIDE;
    const int gq = lid >> 2, t4 = (lid & 3) * 2;
    const uint32_t aAddr = eaU + (uint32_t)((lid & 7) + ((lid >> 3) & 1) * 8) * EA_STRIDE
                         + ((lid >> 4) & 1) * 16;
    const uint32_t b1Off = smb + SOFF_W1C
                         + (uint32_t)((lid & 7) + ((lid >> 4) & 1) * 8) * W1C_STRIDE
                         + ((lid >> 3) & 1) * 16;

    for (int g = blockIdx.x * WPB + wid; g < GROUPS; g += gridDim.x * WPB) {
        const int e0 = g * 16;

        // ---- per-edge meta ----
        int r = 0, c = 0;
        float dx = 0.f, dy = 0.f, dz = 0.f, dd = 0.f;
        if (lid < 16) {
            r = ei[e0 + lid];
            c = ei[NEDGES + e0 + lid];
            dx = pos[3*r+0] - pos[3*c+0];
            dy = pos[3*r+1] - pos[3*c+1];
            dz = pos[3*r+2] - pos[3*c+2];
            dd = sqrtf(dx*dx + dy*dy + dz*dz);
        }
        __syncwarp();

        // ---- S build (fp16): S[i] = P1[row_i] + P2[col_i] + dist_i*W1d  (b1 folded in P1) ----
        #pragma unroll
        for (int pass = 0; pass < 2; ++pass) {
            uint2 p1v[8], p2v[8];
            #pragma unroll
            for (int i = 0; i < 8; ++i) {
                int row = pass * 8 + i;
                int ri = __shfl_sync(0xffffffffu, r, row);
                int ci = __shfl_sync(0xffffffffu, c, row);
                p1v[i] = *(const uint2*)(g_P1 + (size_t)ri * HID + 4 * lid);
                p2v[i] = *(const uint2*)(g_P2 + (size_t)ci * HID + 4 * lid);
            }
            #pragma unroll
            for (int i = 0; i < 8; ++i) {
                int row = pass * 8 + i;
                float di = __shfl_sync(0xffffffffu, dd, row);
                __half2 dh = __float2half2_rn(di);
                __half2 sa = __hfma2(dh, w1dA, __hadd2(*(__half2*)&p1v[i].x, *(__half2*)&p2v[i].x));
                __half2 sb = __hfma2(dh, w1dB, __hadd2(*(__half2*)&p1v[i].y, *(__half2*)&p2v[i].y));
                uint2 pk;
                pk.x = *(uint32_t*)&sa; pk.y = *(uint32_t*)&sb;
                *(uint2*)(Sw + row * S_STRIDE + 8 * lid) = pk;
            }
        }
        // ---- ea tile (fp32 -> fp16, 16 rows x 16 halves) ----
        {
            int erow = lid >> 1, hb = lid & 1;
            const float4* src = (const float4*)(edge_attr + (size_t)(e0 + erow) * 16 + hb * 8);
            float4 u0 = src[0], u1 = src[1];
            __half2 h0 = __floats2half2_rn(u0.x, u0.y), h1 = __floats2half2_rn(u0.z, u0.w);
            __half2 h2 = __floats2half2_rn(u1.x, u1.y), h3 = __floats2half2_rn(u1.z, u1.w);
            uint4 pk;
            pk.x = *(uint32_t*)&h0; pk.y = *(uint32_t*)&h1;
            pk.z = *(uint32_t*)&h2; pk.w = *(uint32_t*)&h3;
            *(uint4*)(eaW + erow * EA_STRIDE + hb * 16) = pk;
        }
        __syncwarp();

        // ---- ea A-frag ----
        uint32_t a0, a1, a2, a3;
        LDSM_X4(a0, a1, a2, a3, aAddr);

        float acc2[4] = {0.f, 0.f, 0.f, 0.f};
        #pragma unroll
        for (int half = 0; half < 2; ++half) {
            // B1 frags for this n-half (ea projection, k=16)
            uint32_t bb[4][4];
            #pragma unroll
            for (int j = 0; j < 4; ++j)
                LDSM_X4(bb[j][0], bb[j][1], bb[j][2], bb[j][3],
                        b1Off + (uint32_t)(half * 64 + j * 16) * W1C_STRIDE);
            float acc1[8][4];
            #pragma unroll
            for (int nt = 0; nt < 8; ++nt) { acc1[nt][0]=0.f; acc1[nt][1]=0.f; acc1[nt][2]=0.f; acc1[nt][3]=0.f; }
            #pragma unroll
            for (int j = 0; j < 4; ++j) {
                MMA16816(acc1[2*j][0],acc1[2*j][1],acc1[2*j][2],acc1[2*j][3], a0,a1,a2,a3, bb[j][0], bb[j][1]);
                MMA16816(acc1[2*j+1][0],acc1[2*j+1][1],acc1[2*j+1][2],acc1[2*j+1][3], a0,a1,a2,a3, bb[j][2], bb[j][3]);
            }
            // epilogue: h = silu_h2(acc1 + S), fp16
            uint32_t hA[8], hB[8];
            #pragma unroll
            for (int nt = 0; nt < 8; ++nt) {
                int colb = (half * 64 + nt * 8 + t4) * 2;       // byte offset into S row
                uint32_t s0 = *(const uint32_t*)(Sw + gq * S_STRIDE + colb);
                uint32_t s1 = *(const uint32_t*)(Sw + (gq + 8) * S_STRIDE + colb);
                __half2 e0h = __floats2half2_rn(acc1[nt][0], acc1[nt][1]);
                __half2 e1h = __floats2half2_rn(acc1[nt][2], acc1[nt][3]);
                __half2 pre0 = __hadd2(e0h, *(__half2*)&s0);
                __half2 pre1 = __hadd2(e1h, *(__half2*)&s1);
                hA[nt] = silu_h2(*(uint32_t*)&pre0);
                hB[nt] = silu_h2(*(uint32_t*)&pre1);
            }
            // GEMM2: acc2 += h(fp16) @ W2 (C-frag -> A-frag reuse)
            #pragma unroll
            for (int s2 = 0; s2 < 4; ++s2) {
                int s = half * 4 + s2;
                MMA16816(acc2[0], acc2[1], acc2[2], acc2[3],
                         hA[2*s2], hB[2*s2], hA[2*s2+1], hB[2*s2+1],
                         b2f[s][0], b2f[s][1]);
            }
        }

        // ---- consolidate w-logits to owning lanes, finish ----
        int m4 = (lid & 7) * 4;
        float q0 = __shfl_sync(0xffffffffu, acc2[0], m4);
        float q1 = __shfl_sync(0xffffffffu, acc2[1], m4);
        float q2 = __shfl_sync(0xffffffffu, acc2[2], m4);
        float q3 = __shfl_sync(0xffffffffu, acc2[3], m4);
        float r0 = __shfl_sync(0xffffffffu, acc2[0], m4 + 1);
        float r2 = __shfl_sync(0xffffffffu, acc2[2], m4 + 1);
        if (lid < 16) {
            float pw0 = (lid < 8) ? q0 : q2;
            float pw1 = (lid < 8) ? q1 : q3;
            float pw2 = (lid < 8) ? r0 : r2;
            float w0  = silu(pw0 + b20);
            float w1v = silu(pw1 + b21);
            float w2v = silu(pw2 + b22);
            float inv = 1.f / fmaxf(dd, 1e-12f);
            float x = dx * inv, y = dy * inv, z = dz * inv;
            const float s3 = 1.7320508075688772f;
            float* o = out + (size_t)r * 9;
            atomicAdd(o + 0, w0);
            atomicAdd(o + 1, x * w1v);
            atomicAdd(o + 2, y * w1v);
            atomicAdd(o + 3, z * w1v);
            atomicAdd(o + 4, s3 * x * z * w2v);
            atomicAdd(o + 5, s3 * x * y * w2v);
            atomicAdd(o + 6, (y * y - 0.5f * (x * x + z * z)) * w2v);
            atomicAdd(o + 7, s3 * y * z * w2v);
            atomicAdd(o + 8, 0.5f * s3 * (z * z - x * x) * w2v);
            atomicAdd(&g_cnt[r], 1.0f);
        }
    }
}

// ---------------- launch ----------------
extern "C" void kernel_launch(void* const* d_in, const int* in_sizes, int n_in,
                              void* d_out, int out_size) {
    const float* node_feat = (const float*)d_in[0];
    const float* node_pos  = (const float*)d_in[1];
    const float* edge_attr = (const float*)d_in[2];
    const float* W1        = (const float*)d_in[3];
    const float* b1        = (const float*)d_in[4];
    const float* W2        = (const float*)d_in[5];
    const float* b2        = (const float*)d_in[6];
    const int*   ei        = (const int*)d_in[7];
    float* out = (float*)d_out;

    cudaFuncSetAttribute(prep_P_kernel, cudaFuncAttributeMaxDynamicSharedMemorySize, PP_SMEM);
    cudaFuncSetAttribute(edge_kernel,   cudaFuncAttributeMaxDynamicSharedMemorySize, SMEM_MAIN);

    zero_kernel<<<512, 256>>>(out);
    prep_feat_kernel<<<(NNODES * HID / 2 + 255) / 256, 256>>>(node_feat);
    prep_w_kernel<<<(35968 + 255) / 256, 256>>>(W1, W2);
    prep_P_kernel<<<196, 512, PP_SMEM>>>(b1);
    edge_kernel<<<152, THREADS, SMEM_MAIN>>>(node_pos, edge_attr, b2, ei, out);
    finalize_kernel<<<512, 256>>>(out);
}

// round 9
// speedup vs baseline: 2.5731x; 1.1046x over previous
#include <cuda_runtime.h>
#include <cuda_fp16.h>
#include <stdint.h>

// ---------------- problem constants ----------------
#define NNODES 50000
#define NEDGES 1000000
#define HID    128
#define THREADS 512
#define WPB    16
#define GROUPS (NEDGES / 16)   // 62500, exact

// ---------------- main-kernel smem layout ----------------
#define S_STRIDE  272                         // 128 halves + 16B pad
#define SOFF_S    0                           // 16 warps * 16 rows * 272 = 69632
#define EA_STRIDE 48
#define SOFF_EA   69632                       // 16*16*48 = 12288 -> 81920
#define W1C_STRIDE 48
#define SOFF_W1C  81920                       // 128*48 = 6144 -> 88064
#define W2T_STRIDE 272
#define SOFF_W2T  88064                       // 8*272 = 2176 -> 90240
#define SMEM_MAIN 90240

// ---------------- prep_P smem layout ----------------
#define PP_BSTR    272
#define PP_SOFF_BA 0                          // 128*272 = 34816
#define PP_SOFF_BB 34816
#define PP_SOFF_AS 69632                      // 16 warps * 16 rows * 272 = 69632
#define PP_SMEM    139264
#define PP_JOBS    6250                       // 3125 tiles x 2 mats

// ---------------- device globals ----------------
__device__ __half g_P1[(size_t)NNODES * HID];     // feat @ W1a^T + b1 (fp16)
__device__ __half g_P2[(size_t)NNODES * HID];     // feat @ W1b^T      (fp16)
__device__ __half g_W1ab[2 * 128 * 128];          // [m][n][k] fp16
__device__ __half g_W1cT[128 * 16];               // [n][k] ea weights
__device__ __half g_W2T[8 * 128];                 // [n(pad8)][k] W2 transposed
__device__ float  g_W1d[128];                     // dist weights
__device__ float  g_cnt[NNODES];

static __device__ __forceinline__ uint32_t smem_u32(const void* p) {
    uint32_t a;
    asm("{ .reg .u64 t; cvta.to.shared.u64 t, %1; cvt.u32.u64 %0, t; }" : "=r"(a) : "l"(p));
    return a;
}
static __device__ __forceinline__ float silu(float x) { return x / (1.f + __expf(-x)); }
// silu on a half2: a = x/2; r = a + a*tanh(a)  (1 MUFU per 2 values)
static __device__ __forceinline__ uint32_t silu_h2(uint32_t x) {
    uint32_t a, t, r;
    asm("mul.rn.f16x2 %0, %1, %2;" : "=r"(a) : "r"(x), "r"(0x38003800u));
    asm("tanh.approx.f16x2 %0, %1;" : "=r"(t) : "r"(a));
    asm("fma.rn.f16x2 %0, %1, %2, %3;" : "=r"(r) : "r"(a), "r"(t), "r"(a));
    return r;
}

#define LDSM_X4(r0,r1,r2,r3,addr) \
    asm volatile("ldmatrix.sync.aligned.m8n8.x4.shared.b16 {%0,%1,%2,%3}, [%4];" \
                 : "=r"(r0), "=r"(r1), "=r"(r2), "=r"(r3) : "r"(addr))
#define MMA16816(d0,d1,d2,d3,a0,a1,a2,a3,b0,b1) \
    asm volatile("mma.sync.aligned.m16n8k16.row.col.f32.f16.f16.f32 " \
                 "{%0,%1,%2,%3}, {%4,%5,%6,%7}, {%8,%9}, {%0,%1,%2,%3};" \
                 : "+f"(d0), "+f"(d1), "+f"(d2), "+f"(d3) \
                 : "r"(a0), "r"(a1), "r"(a2), "r"(a3), "r"(b0), "r"(b1))

// ---------------- fused init: zero out/cnt + weight repack ----------------
// msg order: [0]=dist, [1..128]=feat_row, [129..256]=feat_col, [257..272]=ea
__global__ void init_kernel(float* __restrict__ out,
                            const float* __restrict__ W1,
                            const float* __restrict__ W2) {
    int idx = blockIdx.x * blockDim.x + threadIdx.x;
    int stride = gridDim.x * blockDim.x;
    for (int j = idx; j < NNODES * 9; j += stride) out[j] = 0.f;
    for (int j = idx; j < NNODES; j += stride) g_cnt[j] = 0.f;
    if (idx < 32768) {
        int m = idx >> 14, n = (idx >> 7) & 127, k = idx & 127;
        g_W1ab[idx] = __float2half(W1[(1 + m * 128 + k) * HID + n]);
    } else if (idx < 34816) {
        int j = idx - 32768; int n = j >> 4, c = j & 15;
        g_W1cT[j] = __float2half(W1[(257 + c) * HID + n]);
    } else if (idx < 35840) {
        int j = idx - 34816; int nr = j >> 7, k = j & 127;
        g_W2T[j] = __float2half(nr < 3 ? W2[k * 3 + nr] : 0.f);
    } else if (idx < 35968) {
        int j = idx - 35840;
        g_W1d[j] = W1[j];     // W1[0][n]
    }
}

__global__ void finalize_kernel(float* __restrict__ out) {
    int i = blockIdx.x * blockDim.x + threadIdx.x;
    int stride = gridDim.x * blockDim.x;
    for (int j = i; j < NNODES * 9; j += stride)
        out[j] = out[j] / fmaxf(g_cnt[j / 9], 1.0f);
}

// ---------------- P precompute: persistent, job = (tile, mat) ----------------
__global__ void __launch_bounds__(512, 1)
prep_P_kernel(const float* __restrict__ nf, const float* __restrict__ b1) {
    extern __shared__ char sm[];
    const uint32_t smb = smem_u32(sm);
    int tid = threadIdx.x, wid = tid >> 5, lid = tid & 31;

    {   // stage both B matrices (128 rows x 256B -> stride 272)
        const uint4* srcA = (const uint4*)g_W1ab;
        const uint4* srcB = (const uint4*)(g_W1ab + 16384);
        for (int i = tid; i < 2048; i += 512) {
            int row = i >> 4, p = i & 15;
            *(uint4*)(sm + PP_SOFF_BA + row * PP_BSTR + p * 16) = srcA[i];
            *(uint4*)(sm + PP_SOFF_BB + row * PP_BSTR + p * 16) = srcB[i];
        }
    }
    __syncthreads();

    char* Aw = sm + PP_SOFF_AS + wid * 16 * PP_BSTR;
    const uint32_t aBase = smb + PP_SOFF_AS + (uint32_t)wid * 16 * PP_BSTR
                         + (uint32_t)((lid & 7) + ((lid >> 3) & 1) * 8) * PP_BSTR
                         + ((lid >> 4) & 1) * 16;
    const uint32_t bRowOff = (uint32_t)((lid & 7) + ((lid >> 4) & 1) * 8) * PP_BSTR
                           + ((lid >> 3) & 1) * 16;
    const int gq = lid >> 2, tq = lid & 3;

    const int jstride = gridDim.x * 16;
    for (int job = blockIdx.x * 16 + wid; job < PP_JOBS; job += jstride) {
        const int tile = job >> 1, mat = job & 1;
        const int node0 = tile * 16;

        // stage A: fp32 node_feat -> fp16 smem (batched LDG.128)
        #pragma unroll
        for (int pass = 0; pass < 2; ++pass) {
            float4 v[8];
            #pragma unroll
            for (int i = 0; i < 8; ++i)
                v[i] = *(const float4*)(nf + (size_t)(node0 + pass * 8 + i) * HID + 4 * lid);
            #pragma unroll
            for (int i = 0; i < 8; ++i) {
                __half2 h0 = __floats2half2_rn(v[i].x, v[i].y);
                __half2 h1 = __floats2half2_rn(v[i].z, v[i].w);
                uint2 pk; pk.x = *(uint32_t*)&h0; pk.y = *(uint32_t*)&h1;
                *(uint2*)(Aw + (pass * 8 + i) * PP_BSTR + lid * 8) = pk;
            }
        }
        __syncwarp();

        uint32_t bBase = smb + (mat ? PP_SOFF_BB : PP_SOFF_BA) + bRowOff;
        __half* OUT = mat ? g_P2 : g_P1;
        float acc[16][4];
        #pragma unroll
        for (int nt = 0; nt < 16; ++nt) { acc[nt][0]=0.f; acc[nt][1]=0.f; acc[nt][2]=0.f; acc[nt][3]=0.f; }
        #pragma unroll 1
        for (int ks = 0; ks < 8; ++ks) {
            uint32_t a0,a1,a2,a3;
            LDSM_X4(a0,a1,a2,a3, aBase + ks * 32);
            #pragma unroll
            for (int j = 0; j < 8; ++j) {
                uint32_t b0,b1r,b2,b3;
                LDSM_X4(b0,b1r,b2,b3, bBase + (uint32_t)j * 16 * PP_BSTR + ks * 32);
                MMA16816(acc[2*j][0],acc[2*j][1],acc[2*j][2],acc[2*j][3], a0,a1,a2,a3, b0,b1r);
                MMA16816(acc[2*j+1][0],acc[2*j+1][1],acc[2*j+1][2],acc[2*j+1][3], a0,a1,a2,a3, b2,b3);
            }
        }
        #pragma unroll
        for (int nt = 0; nt < 16; ++nt) {
            int col = nt * 8 + tq * 2;
            float bx = 0.f, by = 0.f;
            if (mat == 0) { bx = b1[col]; by = b1[col + 1]; }
            __half2 v0 = __floats2half2_rn(acc[nt][0] + bx, acc[nt][1] + by);
            __half2 v1 = __floats2half2_rn(acc[nt][2] + bx, acc[nt][3] + by);
            *(__half2*)(OUT + (size_t)(node0 + gq)     * HID + col) = v0;
            *(__half2*)(OUT + (size_t)(node0 + gq + 8) * HID + col) = v1;
        }
        __syncwarp();
    }
}

// ---------------- main edge kernel ----------------
__global__ void __launch_bounds__(THREADS, 1)
edge_kernel(const float* __restrict__ pos,
            const float* __restrict__ edge_attr,
            const float* __restrict__ b2,
            const int*   __restrict__ ei,
            float*       __restrict__ out)
{
    extern __shared__ char sm[];
    const uint32_t smb = smem_u32(sm);
    const int tid = threadIdx.x, wid = tid >> 5, lid = tid & 31;

    // stage W1cT (128 rows x 32B, stride 48) and W2T (8 rows x 256B, stride 272)
    for (int i = tid; i < 256; i += THREADS) {
        int row = i >> 1, p = i & 1;
        *(uint4*)(sm + SOFF_W1C + row * W1C_STRIDE + p * 16) = ((const uint4*)g_W1cT)[i];
    }
    for (int i = tid; i < 128; i += THREADS) {
        int row = i >> 4, p = i & 15;
        *(uint4*)(sm + SOFF_W2T + row * W2T_STRIDE + p * 16) = ((const uint4*)g_W2T)[i];
    }
    // per-lane dist-weight constants (lane covers S cols 4*lid..4*lid+3), half2
    const __half2 w1dA = __floats2half2_rn(g_W1d[4*lid],     g_W1d[4*lid + 1]);
    const __half2 w1dB = __floats2half2_rn(g_W1d[4*lid + 2], g_W1d[4*lid + 3]);
    const float b20 = b2[0], b21 = b2[1], b22 = b2[2];
    __syncthreads();

    // W2 B-frags, permanent in registers (8 ksteps x 2 regs)
    uint32_t b2f[8][2];
    {
        uint32_t addr = smb + SOFF_W2T + (uint32_t)(lid & 7) * W2T_STRIDE + ((lid >> 3) & 1) * 16;
        #pragma unroll
        for (int s = 0; s < 8; ++s)
            asm volatile("ldmatrix.sync.aligned.m8n8.x2.shared.b16 {%0,%1}, [%2];"
                         : "=r"(b2f[s][0]), "=r"(b2f[s][1]) : "r"(addr + s * 32));
    }

    char* Sw  = sm + SOFF_S  + (size_t)wid * 16 * S_STRIDE;
    char* eaW = sm + SOFF_EA + (size_t)wid * 16 * EA_STRIDE;
    const uint32_t eaU = smb + SOFF_EA + (uint32_t)wid * 16 * EA_STRIDE;
    const int gq = lid >> 2, t4 = (lid & 3) * 2;
    const uint32_t aAddr = eaU + (uint32_t)((lid & 7) + ((lid >> 3) & 1) * 8) * EA_STRIDE
                         + ((lid >> 4) & 1) * 16;
    const uint32_t b1Off = smb + SOFF_W1C
                         + (uint32_t)((lid & 7) + ((lid >> 4) & 1) * 8) * W1C_STRIDE
                         + ((lid >> 3) & 1) * 16;

    for (int g = blockIdx.x * WPB + wid; g < GROUPS; g += gridDim.x * WPB) {
        const int e0 = g * 16;

        // ---- per-edge meta ----
        int r = 0, c = 0;
        float dx = 0.f, dy = 0.f, dz = 0.f, dd = 0.f;
        if (lid < 16) {
            r = ei[e0 + lid];
            c = ei[NEDGES + e0 + lid];
            dx = pos[3*r+0] - pos[3*c+0];
            dy = pos[3*r+1] - pos[3*c+1];
            dz = pos[3*r+2] - pos[3*c+2];
            dd = sqrtf(dx*dx + dy*dy + dz*dz);
        }
        __syncwarp();

        // ---- S build (fp16): S[i] = P1[row_i] + P2[col_i] + dist_i*W1d  (b1 folded in P1) ----
        #pragma unroll
        for (int pass = 0; pass < 2; ++pass) {
            uint2 p1v[8], p2v[8];
            #pragma unroll
            for (int i = 0; i < 8; ++i) {
                int row = pass * 8 + i;
                int ri = __shfl_sync(0xffffffffu, r, row);
                int ci = __shfl_sync(0xffffffffu, c, row);
                p1v[i] = *(const uint2*)(g_P1 + (size_t)ri * HID + 4 * lid);
                p2v[i] = *(const uint2*)(g_P2 + (size_t)ci * HID + 4 * lid);
            }
            #pragma unroll
            for (int i = 0; i < 8; ++i) {
                int row = pass * 8 + i;
                float di = __shfl_sync(0xffffffffu, dd, row);
                __half2 dh = __float2half2_rn(di);
                __half2 sa = __hfma2(dh, w1dA, __hadd2(*(__half2*)&p1v[i].x, *(__half2*)&p2v[i].x));
                __half2 sb = __hfma2(dh, w1dB, __hadd2(*(__half2*)&p1v[i].y, *(__half2*)&p2v[i].y));
                uint2 pk;
                pk.x = *(uint32_t*)&sa; pk.y = *(uint32_t*)&sb;
                *(uint2*)(Sw + row * S_STRIDE + 8 * lid) = pk;
            }
        }
        // ---- ea tile (fp32 -> fp16, 16 rows x 16 halves) ----
        {
            int erow = lid >> 1, hb = lid & 1;
            const float4* src = (const float4*)(edge_attr + (size_t)(e0 + erow) * 16 + hb * 8);
            float4 u0 = src[0], u1 = src[1];
            __half2 h0 = __floats2half2_rn(u0.x, u0.y), h1 = __floats2half2_rn(u0.z, u0.w);
            __half2 h2 = __floats2half2_rn(u1.x, u1.y), h3 = __floats2half2_rn(u1.z, u1.w);
            uint4 pk;
            pk.x = *(uint32_t*)&h0; pk.y = *(uint32_t*)&h1;
            pk.z = *(uint32_t*)&h2; pk.w = *(uint32_t*)&h3;
            *(uint4*)(eaW + erow * EA_STRIDE + hb * 16) = pk;
        }
        __syncwarp();

        // ---- ea A-frag ----
        uint32_t a0, a1, a2, a3;
        LDSM_X4(a0, a1, a2, a3, aAddr);

        float acc2[4] = {0.f, 0.f, 0.f, 0.f};
        #pragma unroll
        for (int half = 0; half < 2; ++half) {
            // B1 frags for this n-half (ea projection, k=16)
            uint32_t bb[4][4];
            #pragma unroll
            for (int j = 0; j < 4; ++j)
                LDSM_X4(bb[j][0], bb[j][1], bb[j][2], bb[j][3],
                        b1Off + (uint32_t)(half * 64 + j * 16) * W1C_STRIDE);
            float acc1[8][4];
            #pragma unroll
            for (int nt = 0; nt < 8; ++nt) { acc1[nt][0]=0.f; acc1[nt][1]=0.f; acc1[nt][2]=0.f; acc1[nt][3]=0.f; }
            #pragma unroll
            for (int j = 0; j < 4; ++j) {
                MMA16816(acc1[2*j][0],acc1[2*j][1],acc1[2*j][2],acc1[2*j][3], a0,a1,a2,a3, bb[j][0], bb[j][1]);
                MMA16816(acc1[2*j+1][0],acc1[2*j+1][1],acc1[2*j+1][2],acc1[2*j+1][3], a0,a1,a2,a3, bb[j][2], bb[j][3]);
            }
            // epilogue: h = silu_h2(acc1 + S), fp16
            uint32_t hA[8], hB[8];
            #pragma unroll
            for (int nt = 0; nt < 8; ++nt) {
                int colb = (half * 64 + nt * 8 + t4) * 2;       // byte offset into S row
                uint32_t s0 = *(const uint32_t*)(Sw + gq * S_STRIDE + colb);
                uint32_t s1 = *(const uint32_t*)(Sw + (gq + 8) * S_STRIDE + colb);
                __half2 e0h = __floats2half2_rn(acc1[nt][0], acc1[nt][1]);
                __half2 e1h = __floats2half2_rn(acc1[nt][2], acc1[nt][3]);
                __half2 pre0 = __hadd2(e0h, *(__half2*)&s0);
                __half2 pre1 = __hadd2(e1h, *(__half2*)&s1);
                hA[nt] = silu_h2(*(uint32_t*)&pre0);
                hB[nt] = silu_h2(*(uint32_t*)&pre1);
            }
            // GEMM2: acc2 += h(fp16) @ W2 (C-frag -> A-frag reuse)
            #pragma unroll
            for (int s2 = 0; s2 < 4; ++s2) {
                int s = half * 4 + s2;
                MMA16816(acc2[0], acc2[1], acc2[2], acc2[3],
                         hA[2*s2], hB[2*s2], hA[2*s2+1], hB[2*s2+1],
                         b2f[s][0], b2f[s][1]);
            }
        }

        // ---- consolidate w-logits to owning lanes, finish ----
        int m4 = (lid & 7) * 4;
        float q0 = __shfl_sync(0xffffffffu, acc2[0], m4);
        float q1 = __shfl_sync(0xffffffffu, acc2[1], m4);
        float q2 = __shfl_sync(0xffffffffu, acc2[2], m4);
        float q3 = __shfl_sync(0xffffffffu, acc2[3], m4);
        float r0 = __shfl_sync(0xffffffffu, acc2[0], m4 + 1);
        float r2 = __shfl_sync(0xffffffffu, acc2[2], m4 + 1);
        if (lid < 16) {
            float pw0 = (lid < 8) ? q0 : q2;
            float pw1 = (lid < 8) ? q1 : q3;
            float pw2 = (lid < 8) ? r0 : r2;
            float w0  = silu(pw0 + b20);
            float w1v = silu(pw1 + b21);
            float w2v = silu(pw2 + b22);
            float inv = 1.f / fmaxf(dd, 1e-12f);
            float x = dx * inv, y = dy * inv, z = dz * inv;
            const float s3 = 1.7320508075688772f;
            float* o = out + (size_t)r * 9;
            atomicAdd(o + 0, w0);
            atomicAdd(o + 1, x * w1v);
            atomicAdd(o + 2, y * w1v);
            atomicAdd(o + 3, z * w1v);
            atomicAdd(o + 4, s3 * x * z * w2v);
            atomicAdd(o + 5, s3 * x * y * w2v);
            atomicAdd(o + 6, (y * y - 0.5f * (x * x + z * z)) * w2v);
            atomicAdd(o + 7, s3 * y * z * w2v);
            atomicAdd(o + 8, 0.5f * s3 * (z * z - x * x) * w2v);
            atomicAdd(&g_cnt[r], 1.0f);
        }
    }
}

// ---------------- launch ----------------
extern "C" void kernel_launch(void* const* d_in, const int* in_sizes, int n_in,
                              void* d_out, int out_size) {
    const float* node_feat = (const float*)d_in[0];
    const float* node_pos  = (const float*)d_in[1];
    const float* edge_attr = (const float*)d_in[2];
    const float* W1        = (const float*)d_in[3];
    const float* b1        = (const float*)d_in[4];
    const float* W2        = (const float*)d_in[5];
    const float* b2        = (const float*)d_in[6];
    const int*   ei        = (const int*)d_in[7];
    float* out = (float*)d_out;

    cudaFuncSetAttribute(prep_P_kernel, cudaFuncAttributeMaxDynamicSharedMemorySize, PP_SMEM);
    cudaFuncSetAttribute(edge_kernel,   cudaFuncAttributeMaxDynamicSharedMemorySize, SMEM_MAIN);

    init_kernel<<<512, 256>>>(out, W1, W2);
    prep_P_kernel<<<152, 512, PP_SMEM>>>(node_feat, b1);
    edge_kernel<<<152, THREADS, SMEM_MAIN>>>(node_pos, edge_attr, b2, ei, out);
    finalize_kernel<<<512, 256>>>(out);
}